// round 5
// baseline (speedup 1.0000x reference)
#include <cuda_runtime.h>
#include <cstdint>

// AdaptiveSample, cp.async double-buffered staging (4 phases x 8 channels):
//   weights: softmax over 15 sampled taps of valid*posw*guide (per pixel)
//   out[b,c,h,w] = sum_s wv[s] * feat[b,c,h+dy_s,w+dx_s]  (zero-pad via masked weights)
//   second output = passthrough copy of features.

namespace {
constexpr int H  = 256;
constexpr int W  = 512;
constexpr int C  = 32;
constexpr int S  = 15;
constexpr int KS = 5;
constexpr int KK = 25;
constexpr int HW = H * W;

constexpr int BW = 32;            // tile width (warp-coalesced)
constexpr int BH = 8;             // tile height
constexpr int NT = BW * BH;       // 256 threads

constexpr int FP   = 48;          // smem pitch (floats): cols [w0-8, w0+40), 16B-aligned
constexpr int FR   = 12;          // smem rows: [h0-2, h0+10)
constexpr int SLOT = FP * FR;     // 576 floats per channel
constexpr int PC   = 8;           // channels per phase
constexpr int NP   = C / PC;      // 4 phases
constexpr int BUFF = PC * SLOT;   // 4608 floats per buffer

constexpr int GBUF = BH * BW * KK;   // guide tile floats (6400)
constexpr int BUF0 = GBUF;           // buffer 0: [6400, 11008)
constexpr int BUF1 = 0;              // buffer 1 reuses guide region [0, 4608)
constexpr int SHN  = GBUF + BUFF;    // 11008 floats = 43 KB
}

__device__ __forceinline__ void cp_async16(uint32_t dst_smem, const void* src) {
    asm volatile("cp.async.ca.shared.global [%0], [%1], 16;\n" :: "r"(dst_smem), "l"(src));
}
__device__ __forceinline__ void cp_commit() { asm volatile("cp.async.commit_group;\n"); }
__device__ __forceinline__ void cp_wait0()  { asm volatile("cp.async.wait_group 0;\n"); }

__global__ __launch_bounds__(NT, 5)
void adaptive_sample_kernel(const float* __restrict__ depth,
                            const float* __restrict__ features,
                            const float* __restrict__ guide,
                            const int*   __restrict__ sidx,
                            float* __restrict__ out,
                            float* __restrict__ outf,
                            int do_copy)
{
    __shared__ float       sh[SHN];
    __shared__ float       sh_posw[S];
    __shared__ int         sh_k[S];
    __shared__ signed char sh_dy[S], sh_dx[S];

    const int tx  = threadIdx.x;
    const int ty  = threadIdx.y;
    const int tid = ty * BW + tx;
    const int w0  = blockIdx.x * BW;
    const int h0  = blockIdx.y * BH;
    const int b   = blockIdx.z;

    const uint32_t sbase = (uint32_t)__cvta_generic_to_shared(sh);

    // ---- tap metadata (one thread; S=15 trivial) ----
    if (tid == 0) {
        float pw[S];
        float sum = 0.f;
        #pragma unroll
        for (int s = 0; s < S; ++s) {
            int k  = sidx[s];
            int px = k % KS;
            int py = k / KS;
            float fx = (float)px - 2.f;
            float fy = (float)py - 2.f;
            float v  = __expf(-0.5f * sqrtf(fx * fx + fy * fy));
            pw[s] = v; sum += v;
            sh_k[s]  = k;
            sh_dy[s] = (signed char)(py - 2);
            sh_dx[s] = (signed char)(px - 2);
        }
        float inv = 1.f / sum;
        #pragma unroll
        for (int s = 0; s < S; ++s) sh_posw[s] = pw[s] * inv;
    }

    const float* fbase = features + (size_t)b * C * HW;

    // ---- feature staging for one phase (cp.async, 16B chunks, clamped halo) ----
    auto stage = [&](int g, int bufoff) {
        const float* fb = fbase + (size_t)(g * PC) * HW;
        #pragma unroll
        for (int it = 0; it < (PC * FR * (FP / 4) + NT - 1) / NT; ++it) {  // 5
            int u = tid + it * NT;
            if (u < PC * FR * (FP / 4)) {
                int ch  = u / (FR * FP / 4);            // /144
                int rem = u - ch * (FR * FP / 4);
                int r   = rem / (FP / 4);               // /12
                int q   = rem - r * (FP / 4);
                int gh  = min(max(h0 + r - 2, 0), H - 1);
                int gc  = min(max(w0 - 8 + q * 4, 0), W - 4);
                cp_async16(sbase + (uint32_t)(bufoff + ch * SLOT + r * FP + q * 4) * 4u,
                           fb + (size_t)ch * HW + gh * W + gc);
            }
        }
        cp_commit();
    };

    // ---- stage guide tile (float4 LDG -> STS) + kick off phase-0 feature staging ----
    #pragma unroll
    for (int it = 0; it < (GBUF / 4 + NT - 1) / NT; ++it) {
        int i4 = tid + it * NT;
        if (i4 < GBUF / 4) {
            int row = i4 / (BW * KK / 4);
            int in4 = i4 - row * (BW * KK / 4);
            const float4* src = reinterpret_cast<const float4*>(
                guide + (((size_t)b * H + (h0 + row)) * W + w0) * KK) + in4;
            reinterpret_cast<float4*>(sh + row * BW * KK)[in4] = *src;
        }
    }
    stage(0, BUF0);

    // ---- passthrough copy (gmem->gmem float4; overlaps staging latency) ----
    if (do_copy) {
        float* ocbase = outf + (size_t)b * C * HW;
        #pragma unroll
        for (int it = 0; it < (C * BH * BW / 4) / NT; ++it) {   // 8
            int i   = tid + it * NT;
            int c   = i >> 6;
            int rem = i & 63;
            int r   = rem >> 3;
            int q4  = rem & 7;
            size_t off = (size_t)c * HW + (size_t)(h0 + r) * W + w0 + q4 * 4;
            float4 v = __ldg(reinterpret_cast<const float4*>(fbase + off));
            *reinterpret_cast<float4*>(ocbase + off) = v;
        }
    }
    __syncthreads();   // guide tile visible

    const int h = h0 + ty;
    const int w = w0 + tx;

    // ---- per-pixel softmax weights + tap addresses ----
    const float* drow = depth + (size_t)b * HW;
    const float* gpix = sh + (ty * BW + tx) * KK;   // lane stride 25: conflict-free

    float wv[S];
    int   addr[S];
    unsigned ibm  = 0u;
    float    gmax = 0.f;  // logits >= 0
    #pragma unroll
    for (int s = 0; s < S; ++s) {
        int dy = (int)sh_dy[s], dx = (int)sh_dx[s];
        int hh = h + dy, ww = w + dx;
        bool ib = ((unsigned)hh < (unsigned)H) && ((unsigned)ww < (unsigned)W);
        float d = ib ? __ldg(drow + hh * W + ww) : 0.f;
        bool valid = ib && (d > 0.f) && (d < 192.0f);
        float logit = valid ? sh_posw[s] * gpix[sh_k[s]] : 0.f;
        wv[s] = logit;
        gmax  = fmaxf(gmax, logit);
        ibm  |= (unsigned)ib << s;
        addr[s] = (ty + 2 + dy) * FP + (tx + 8 + dx);
    }
    float esum = 0.f;
    #pragma unroll
    for (int s = 0; s < S; ++s) { wv[s] = __expf(wv[s] - gmax); esum += wv[s]; }
    float inv = 1.f / esum;
    #pragma unroll
    for (int s = 0; s < S; ++s)
        wv[s] = ((ibm >> s) & 1u) ? wv[s] * inv : 0.f;  // OOB tap == zero-padded feature

    cp_wait0();
    __syncthreads();   // weights done (guide region dead), buffer 0 ready

    float* obase = out + (size_t)b * C * HW + (size_t)h * W + w;

    #pragma unroll
    for (int g = 0; g < NP; ++g) {
        const int bufoff = (g & 1) ? BUF1 : BUF0;
        if (g + 1 < NP) stage(g + 1, (g & 1) ? BUF0 : BUF1);

        const float* bp = sh + bufoff;
        #pragma unroll
        for (int qq = 0; qq < PC; qq += 4) {
            const float* p0 = bp + (qq + 0) * SLOT;
            const float* p1 = bp + (qq + 1) * SLOT;
            const float* p2 = bp + (qq + 2) * SLOT;
            const float* p3 = bp + (qq + 3) * SLOT;
            float a0 = 0.f, a1 = 0.f, a2 = 0.f, a3 = 0.f;
            #pragma unroll
            for (int s = 0; s < S; ++s) {
                float wt = wv[s];
                int   o  = addr[s];
                a0 = fmaf(wt, p0[o], a0);
                a1 = fmaf(wt, p1[o], a1);
                a2 = fmaf(wt, p2[o], a2);
                a3 = fmaf(wt, p3[o], a3);
            }
            obase[(size_t)(g * PC + qq + 0) * HW] = a0;
            obase[(size_t)(g * PC + qq + 1) * HW] = a1;
            obase[(size_t)(g * PC + qq + 2) * HW] = a2;
            obase[(size_t)(g * PC + qq + 3) * HW] = a3;
        }

        if (g + 1 < NP) cp_wait0();
        __syncthreads();
    }
}

extern "C" void kernel_launch(void* const* d_in, const int* in_sizes, int n_in,
                              void* d_out, int out_size)
{
    const float* depth    = (const float*)d_in[0];
    const float* features = (const float*)d_in[1];
    const float* guide    = (const float*)d_in[2];
    const int*   sidx     = (const int*)d_in[3];

    float* out = (float*)d_out;
    const int featN = in_sizes[1];                       // B*C*H*W
    const int do_copy = (out_size >= 2 * featN) ? 1 : 0; // tuple output: (out, features)
    float* outf = out + featN;

    dim3 block(BW, BH);
    dim3 grid(W / BW, H / BH, 2 /*B*/);
    adaptive_sample_kernel<<<grid, block>>>(depth, features, guide, sidx,
                                            out, outf, do_copy);
}